// round 1
// baseline (speedup 1.0000x reference)
#include <cuda_runtime.h>
#include <math.h>

// ---------------- problem constants ----------------
#define B_    64
#define T_    12
#define N_    512
#define H_    12
#define RNN_  64
#define DEC_  128
#define MEMN_ 20
#define MEMD_ 64
#define EMB_  10
#define ENC_C_  65
#define ENC_CH_ 195
#define DEC_C_  130
#define DEC_CH_ 390
#define ROWS_ (B_ * N_)   // 32768

// ---------------- scratch (device globals; no allocations) ----------------
__device__ float g_h[ROWS_ * RNN_];                 // encoder hidden
__device__ float g_haug[ROWS_ * DEC_];              // [h_t, h_att] / decoder hidden
__device__ float g_cheb[ROWS_ * DEC_CH_];           // cheb feature buffer (enc uses ld=195)
__device__ float g_zr[ROWS_ * 2 * DEC_];            // gate activations (enc ld=128, dec ld=256)
__device__ float g_emb[ROWS_ * EMB_];               // node embeddings
__device__ float g_support[(size_t)B_ * N_ * N_];   // batched adjacency
__device__ float g_go[ROWS_];                       // decoder feedback output
__device__ int   g_pos[ROWS_];
__device__ int   g_pos_his[ROWS_];

// ---------------- generic tiled SGEMM: C[b] = alpha * A[b] @ X[b] (- SUB[b]) ----------------
template<int BM,int BN,int BK,int TM,int TN>
__global__ void __launch_bounds__((BM/TM)*(BN/TN))
gemm_graph_k(const float* __restrict__ Aall, int lda, long long strideA,
             const float* __restrict__ Xall, int ldx, long long strideX,
             float* __restrict__ Call, int ldc, long long strideC,
             const float* __restrict__ SUBall,
             int K, int Ncol, float alpha)
{
    constexpr int THREADS = (BM/TM)*(BN/TN);
    const int b = blockIdx.z;
    const float* A = Aall + strideA * (long long)b;
    const float* X = Xall + strideX * (long long)b;
    float* C = Call + strideC * (long long)b;
    const float* SUB = SUBall ? SUBall + strideX * (long long)b : nullptr;

    const int rowBlk = blockIdx.y * BM;
    const int colBlk = blockIdx.x * BN;
    const int tid = threadIdx.x;
    const int tcol = tid % (BN / TN);
    const int trow = tid / (BN / TN);

    __shared__ float As[BK][BM + 4];
    __shared__ float Xs[BK][BN + 4];

    float acc[TM][TN];
#pragma unroll
    for (int i = 0; i < TM; i++)
#pragma unroll
        for (int j = 0; j < TN; j++) acc[i][j] = 0.f;

    for (int kt = 0; kt < K; kt += BK) {
#pragma unroll
        for (int i = 0; i < (BM * BK) / THREADS; i++) {
            int idx = tid + i * THREADS;
            int m = idx / BK, kk = idx % BK;
            int kg = kt + kk;
            As[kk][m] = (kg < K) ? A[(long long)(rowBlk + m) * lda + kg] : 0.f;
        }
#pragma unroll
        for (int i = 0; i < (BK * BN) / THREADS; i++) {
            int idx = tid + i * THREADS;
            int kk = idx / BN, c = idx % BN;
            int kg = kt + kk, cg = colBlk + c;
            Xs[kk][c] = (kg < K && cg < Ncol) ? X[(long long)kg * ldx + cg] : 0.f;
        }
        __syncthreads();
#pragma unroll
        for (int k = 0; k < BK; k++) {
            float a[TM], xv[TN];
#pragma unroll
            for (int i = 0; i < TM; i++) a[i] = As[k][trow * TM + i];
#pragma unroll
            for (int j = 0; j < TN; j++) xv[j] = Xs[k][tcol * TN + j];
#pragma unroll
            for (int i = 0; i < TM; i++)
#pragma unroll
                for (int j = 0; j < TN; j++) acc[i][j] += a[i] * xv[j];
        }
        __syncthreads();
    }
#pragma unroll
    for (int i = 0; i < TM; i++) {
        int r = rowBlk + trow * TM + i;
#pragma unroll
        for (int j = 0; j < TN; j++) {
            int c = colBlk + tcol * TN + j;
            if (c < Ncol) {
                float v = alpha * acc[i][j];
                if (SUB) v -= SUB[(long long)r * ldx + c];
                C[(long long)r * ldc + c] = v;
            }
        }
    }
}

// ---------------- dense layer GEMM: (M,K) @ (K,Ncol) + bias, fused activation ----------------
// mode 0: linear, mode 1: sigmoid, mode 2: tanh + GRU update (h = r*h + (1-r)*tanh(v))
template<int BM,int BN,int BK,int TM,int TN>
__global__ void __launch_bounds__((BM/TM)*(BN/TN))
gemm_dense_k(const float* __restrict__ F, int ldf,
             const float* __restrict__ W,
             const float* __restrict__ bias,
             float* __restrict__ C, int ldc,
             int K, int Ncol, int mode,
             float* __restrict__ Hupd,
             const float* __restrict__ ZR, int ldzr)
{
    constexpr int THREADS = (BM/TM)*(BN/TN);
    const int rowBlk = blockIdx.y * BM;
    const int colBlk = blockIdx.x * BN;
    const int tid = threadIdx.x;
    const int tcol = tid % (BN / TN);
    const int trow = tid / (BN / TN);

    __shared__ float As[BK][BM + 4];
    __shared__ float Ws[BK][BN + 4];

    float acc[TM][TN];
#pragma unroll
    for (int i = 0; i < TM; i++)
#pragma unroll
        for (int j = 0; j < TN; j++) acc[i][j] = 0.f;

    for (int kt = 0; kt < K; kt += BK) {
#pragma unroll
        for (int i = 0; i < (BM * BK) / THREADS; i++) {
            int idx = tid + i * THREADS;
            int m = idx / BK, kk = idx % BK;
            int kg = kt + kk;
            As[kk][m] = (kg < K) ? F[(long long)(rowBlk + m) * ldf + kg] : 0.f;
        }
#pragma unroll
        for (int i = 0; i < (BK * BN) / THREADS; i++) {
            int idx = tid + i * THREADS;
            int kk = idx / BN, c = idx % BN;
            int kg = kt + kk, cg = colBlk + c;
            Ws[kk][c] = (kg < K && cg < Ncol) ? W[(long long)kg * Ncol + cg] : 0.f;
        }
        __syncthreads();
#pragma unroll
        for (int k = 0; k < BK; k++) {
            float a[TM], wv[TN];
#pragma unroll
            for (int i = 0; i < TM; i++) a[i] = As[k][trow * TM + i];
#pragma unroll
            for (int j = 0; j < TN; j++) wv[j] = Ws[k][tcol * TN + j];
#pragma unroll
            for (int i = 0; i < TM; i++)
#pragma unroll
                for (int j = 0; j < TN; j++) acc[i][j] += a[i] * wv[j];
        }
        __syncthreads();
    }
#pragma unroll
    for (int i = 0; i < TM; i++) {
        int r = rowBlk + trow * TM + i;
#pragma unroll
        for (int j = 0; j < TN; j++) {
            int c = colBlk + tcol * TN + j;
            if (c < Ncol) {
                float v = acc[i][j] + bias[c];
                if (mode == 0) {
                    C[(long long)r * ldc + c] = v;
                } else if (mode == 1) {
                    C[(long long)r * ldc + c] = 1.f / (1.f + expf(-v));
                } else {
                    float rg = ZR[(long long)r * ldzr + Ncol + c];
                    long long hi = (long long)r * Ncol + c;
                    float hv = Hupd[hi];
                    Hupd[hi] = rg * hv + (1.f - rg) * tanhf(v);
                }
            }
        }
    }
}

// ---------------- elementwise builders ----------------
__global__ void build_enc_inp_k(const float* __restrict__ xp, int t) {
    int idx = blockIdx.x * blockDim.x + threadIdx.x;
    if (idx >= ROWS_ * ENC_C_) return;
    int row = idx / ENC_C_, c = idx % ENC_C_;
    int b = row / N_, n = row % N_;
    float v = (c == 0) ? xp[((long long)b * T_ + t) * N_ + n]
                       : g_h[(long long)row * RNN_ + (c - 1)];
    g_cheb[(long long)row * ENC_CH_ + c] = v;
}

__global__ void build_enc_cand_k(const float* __restrict__ xp, int t) {
    int idx = blockIdx.x * blockDim.x + threadIdx.x;
    if (idx >= ROWS_ * ENC_C_) return;
    int row = idx / ENC_C_, c = idx % ENC_C_;
    int b = row / N_, n = row % N_;
    float v;
    if (c == 0) v = xp[((long long)b * T_ + t) * N_ + n];
    else v = g_zr[(long long)row * (2 * RNN_) + (c - 1)] * g_h[(long long)row * RNN_ + (c - 1)];
    g_cheb[(long long)row * ENC_CH_ + c] = v;
}

__global__ void build_dec_inp_k(const float* __restrict__ ycov, int t) {
    int idx = blockIdx.x * blockDim.x + threadIdx.x;
    if (idx >= ROWS_ * DEC_C_) return;
    int row = idx / DEC_C_, c = idx % DEC_C_;
    int b = row / N_, n = row % N_;
    float v;
    if (c == 0)      v = (t == 0) ? 0.f : g_go[row];
    else if (c == 1) v = ycov[((long long)b * H_ + t) * N_ + n];
    else             v = g_haug[(long long)row * DEC_ + (c - 2)];
    g_cheb[(long long)row * DEC_CH_ + c] = v;
}

__global__ void build_dec_cand_k(const float* __restrict__ ycov, int t) {
    int idx = blockIdx.x * blockDim.x + threadIdx.x;
    if (idx >= ROWS_ * DEC_C_) return;
    int row = idx / DEC_C_, c = idx % DEC_C_;
    int b = row / N_, n = row % N_;
    float v;
    if (c == 0)      v = (t == 0) ? 0.f : g_go[row];
    else if (c == 1) v = ycov[((long long)b * H_ + t) * N_ + n];
    else             v = g_zr[(long long)row * (2 * DEC_) + (c - 2)] * g_haug[(long long)row * DEC_ + (c - 2)];
    g_cheb[(long long)row * DEC_CH_ + c] = v;
}

// ---------------- memory query: q = h@Wq, att = softmax(q@Mem^T), value, argmax ----------------
__global__ void query_k(const float* __restrict__ Wq, const float* __restrict__ Mem,
                        int write_value, int* __restrict__ posOut) {
    int row = blockIdx.x;
    int tid = threadIdx.x;   // 64 threads
    __shared__ float hs[RNN_], q[MEMD_], att[MEMN_];
    hs[tid] = g_h[(long long)row * RNN_ + tid];
    __syncthreads();
    float s = 0.f;
#pragma unroll
    for (int k = 0; k < RNN_; k++) s += hs[k] * Wq[k * MEMD_ + tid];
    q[tid] = s;
    __syncthreads();
    if (tid < MEMN_) {
        float l = 0.f;
#pragma unroll
        for (int k = 0; k < MEMD_; k++) l += q[k] * Mem[tid * MEMD_ + k];
        att[tid] = l;
    }
    __syncthreads();
    if (tid == 0) {
        float mx = att[0]; int am = 0;
        for (int m = 1; m < MEMN_; m++) if (att[m] > mx) { mx = att[m]; am = m; }
        float sum = 0.f;
        for (int m = 0; m < MEMN_; m++) { float e = expf(att[m] - mx); att[m] = e; sum += e; }
        float inv = 1.f / sum;
        for (int m = 0; m < MEMN_; m++) att[m] *= inv;
        posOut[row] = am;
    }
    __syncthreads();
    if (write_value) {
        float v = 0.f;
#pragma unroll
        for (int m = 0; m < MEMN_; m++) v += att[m] * Mem[m * MEMD_ + tid];
        g_haug[(long long)row * DEC_ + RNN_ + tid] = v;
        g_haug[(long long)row * DEC_ + tid] = hs[tid];
    }
}

// ---------------- latent distance ----------------
__global__ void latent_k(const float* __restrict__ Mem, const float* __restrict__ laW,
                         const float* __restrict__ laB, float* __restrict__ out) {
    int idx = blockIdx.x * blockDim.x + threadIdx.x;
    if (idx >= ROWS_) return;
    int i0 = g_pos[idx], i1 = g_pos_his[idx];
    float s = laB[0];
#pragma unroll
    for (int k = 0; k < MEMD_; k++) s += (Mem[i0 * MEMD_ + k] - Mem[i1 * MEMD_ + k]) * laW[k];
    out[(long long)B_ * H_ * N_ + idx] = 1.f / (1.f + expf(-s));
}

// ---------------- support: softmax_m(relu(e_n . e_m)) ----------------
__global__ void build_support_k() {
    const int b = blockIdx.x;
    const int rt = blockIdx.y;     // 32 tiles of 16 rows
    const int tid = threadIdx.x;   // 256
    __shared__ float e[N_ * EMB_];
    __shared__ float lbuf[N_];
    __shared__ float red[256];
    for (int i = tid; i < N_ * EMB_; i += 256) e[i] = g_emb[(long long)b * N_ * EMB_ + i];
    __syncthreads();
    for (int rr = 0; rr < 16; rr++) {
        int row = rt * 16 + rr;
        float er[EMB_];
#pragma unroll
        for (int k = 0; k < EMB_; k++) er[k] = e[row * EMB_ + k];
        for (int m = tid; m < N_; m += 256) {
            float d = 0.f;
#pragma unroll
            for (int k = 0; k < EMB_; k++) d += er[k] * e[m * EMB_ + k];
            lbuf[m] = fmaxf(d, 0.f);
        }
        __syncthreads();
        float mx = -1e30f;
        for (int m = tid; m < N_; m += 256) mx = fmaxf(mx, lbuf[m]);
        red[tid] = mx;
        __syncthreads();
        for (int s2 = 128; s2 > 0; s2 >>= 1) { if (tid < s2) red[tid] = fmaxf(red[tid], red[tid + s2]); __syncthreads(); }
        mx = red[0];
        __syncthreads();
        float ps = 0.f;
        for (int m = tid; m < N_; m += 256) { float ev = expf(lbuf[m] - mx); lbuf[m] = ev; ps += ev; }
        red[tid] = ps;
        __syncthreads();
        for (int s2 = 128; s2 > 0; s2 >>= 1) { if (tid < s2) red[tid] += red[tid + s2]; __syncthreads(); }
        float inv = 1.f / red[0];
        __syncthreads();
        for (int m = tid; m < N_; m += 256)
            g_support[((size_t)b * N_ + row) * N_ + m] = lbuf[m] * inv;
        __syncthreads();
    }
}

// ---------------- projection: go = h @ proj_W + b; write to out[b,t,n] ----------------
__global__ void proj_k(const float* __restrict__ W, const float* __restrict__ bs,
                       float* __restrict__ out, int t) {
    int gid = blockIdx.x * blockDim.x + threadIdx.x;
    int warp = gid >> 5, lane = gid & 31;
    if (warp >= ROWS_) return;
    float s = 0.f;
#pragma unroll
    for (int k = lane; k < DEC_; k += 32) s += g_haug[(long long)warp * DEC_ + k] * W[k];
#pragma unroll
    for (int o = 16; o > 0; o >>= 1) s += __shfl_down_sync(0xffffffffu, s, o);
    if (lane == 0) {
        float v = s + bs[0];
        g_go[warp] = v;
        int b = warp / N_, n = warp % N_;
        out[((long long)b * H_ + t) * N_ + n] = v;
    }
}

// ---------------- host orchestration ----------------
extern "C" void kernel_launch(void* const* d_in, const int* in_sizes, int n_in,
                              void* d_out, int out_size) {
    const float* x     = (const float*)d_in[0];
    // d_in[1] = x_cov (unused by reference)
    const float* x_his = (const float*)d_in[2];
    const float* y_cov = (const float*)d_in[3];
    const float* adj   = (const float*)d_in[4];
    const float* egW   = (const float*)d_in[5];
    const float* egB   = (const float*)d_in[6];
    const float* euW   = (const float*)d_in[7];
    const float* euB   = (const float*)d_in[8];
    const float* dgW   = (const float*)d_in[9];
    const float* dgB   = (const float*)d_in[10];
    const float* duW   = (const float*)d_in[11];
    const float* duB   = (const float*)d_in[12];
    const float* Mem   = (const float*)d_in[13];
    const float* Wq    = (const float*)d_in[14];
    const float* hyW   = (const float*)d_in[15];
    const float* hyB   = (const float*)d_in[16];
    const float* laW   = (const float*)d_in[17];
    const float* laB   = (const float*)d_in[18];
    const float* prW   = (const float*)d_in[19];
    const float* prB   = (const float*)d_in[20];
    float* out = (float*)d_out;

    float *h, *cheb, *zr, *haug, *emb, *support;
    int *pos, *poshis;
    cudaGetSymbolAddress((void**)&h, g_h);
    cudaGetSymbolAddress((void**)&cheb, g_cheb);
    cudaGetSymbolAddress((void**)&zr, g_zr);
    cudaGetSymbolAddress((void**)&haug, g_haug);
    cudaGetSymbolAddress((void**)&emb, g_emb);
    cudaGetSymbolAddress((void**)&support, g_support);
    cudaGetSymbolAddress((void**)&pos, g_pos);
    cudaGetSymbolAddress((void**)&poshis, g_pos_his);

    const long long encBS = (long long)N_ * ENC_CH_;   // cheb batch stride (encoder view)
    const long long decBS = (long long)N_ * DEC_CH_;
    const dim3 ggEnc((ENC_C_ + 31) / 32, N_ / 64, B_);
    const dim3 ggDec((DEC_C_ + 31) / 32, N_ / 64, B_);

    auto enc_step = [&](const float* xp, int t) {
        int nel = ROWS_ * ENC_C_;
        build_enc_inp_k<<<(nel + 255) / 256, 256>>>(xp, t);
        gemm_graph_k<64,32,16,4,2><<<ggEnc, 256>>>(adj, N_, 0LL,
            cheb, ENC_CH_, encBS, cheb + ENC_C_, ENC_CH_, encBS, nullptr, N_, ENC_C_, 1.f);
        gemm_graph_k<64,32,16,4,2><<<ggEnc, 256>>>(adj, N_, 0LL,
            cheb + ENC_C_, ENC_CH_, encBS, cheb + 2 * ENC_C_, ENC_CH_, encBS, cheb, N_, ENC_C_, 2.f);
        gemm_dense_k<64,64,16,4,4><<<dim3(2, ROWS_ / 64), 256>>>(cheb, ENC_CH_, egW, egB,
            zr, 2 * RNN_, ENC_CH_, 2 * RNN_, 1, nullptr, nullptr, 0);
        build_enc_cand_k<<<(nel + 255) / 256, 256>>>(xp, t);
        gemm_graph_k<64,32,16,4,2><<<ggEnc, 256>>>(adj, N_, 0LL,
            cheb, ENC_CH_, encBS, cheb + ENC_C_, ENC_CH_, encBS, nullptr, N_, ENC_C_, 1.f);
        gemm_graph_k<64,32,16,4,2><<<ggEnc, 256>>>(adj, N_, 0LL,
            cheb + ENC_C_, ENC_CH_, encBS, cheb + 2 * ENC_C_, ENC_CH_, encBS, cheb, N_, ENC_C_, 2.f);
        gemm_dense_k<64,64,16,4,4><<<dim3(1, ROWS_ / 64), 256>>>(cheb, ENC_CH_, euW, euB,
            nullptr, 0, ENC_CH_, RNN_, 2, h, zr, 2 * RNN_);
    };

    // ---- encoder on x ----
    cudaMemsetAsync(h, 0, sizeof(float) * (size_t)ROWS_ * RNN_);
    for (int t = 0; t < T_; t++) enc_step(x, t);
    query_k<<<ROWS_, 64>>>(Wq, Mem, 1, pos);

    // ---- encoder on x_his ----
    cudaMemsetAsync(h, 0, sizeof(float) * (size_t)ROWS_ * RNN_);
    for (int t = 0; t < T_; t++) enc_step(x_his, t);
    query_k<<<ROWS_, 64>>>(Wq, Mem, 0, poshis);

    // ---- latent distance ----
    latent_k<<<(ROWS_ + 255) / 256, 256>>>(Mem, laW, laB, out);

    // ---- node embeddings + support ----
    gemm_dense_k<64,64,16,4,4><<<dim3(1, ROWS_ / 64), 256>>>(haug, DEC_, hyW, hyB,
        emb, EMB_, DEC_, EMB_, 0, nullptr, nullptr, 0);
    build_support_k<<<dim3(B_, N_ / 16), 256>>>();

    // ---- decoder ----
    for (int t = 0; t < H_; t++) {
        int nel = ROWS_ * DEC_C_;
        build_dec_inp_k<<<(nel + 255) / 256, 256>>>(y_cov, t);
        gemm_graph_k<64,32,16,4,2><<<ggDec, 256>>>(support, N_, (long long)N_ * N_,
            cheb, DEC_CH_, decBS, cheb + DEC_C_, DEC_CH_, decBS, nullptr, N_, DEC_C_, 1.f);
        gemm_graph_k<64,32,16,4,2><<<ggDec, 256>>>(support, N_, (long long)N_ * N_,
            cheb + DEC_C_, DEC_CH_, decBS, cheb + 2 * DEC_C_, DEC_CH_, decBS, cheb, N_, DEC_C_, 2.f);
        gemm_dense_k<64,64,16,4,4><<<dim3(4, ROWS_ / 64), 256>>>(cheb, DEC_CH_, dgW, dgB,
            zr, 2 * DEC_, DEC_CH_, 2 * DEC_, 1, nullptr, nullptr, 0);
        build_dec_cand_k<<<(nel + 255) / 256, 256>>>(y_cov, t);
        gemm_graph_k<64,32,16,4,2><<<ggDec, 256>>>(support, N_, (long long)N_ * N_,
            cheb, DEC_CH_, decBS, cheb + DEC_C_, DEC_CH_, decBS, nullptr, N_, DEC_C_, 1.f);
        gemm_graph_k<64,32,16,4,2><<<ggDec, 256>>>(support, N_, (long long)N_ * N_,
            cheb + DEC_C_, DEC_CH_, decBS, cheb + 2 * DEC_C_, DEC_CH_, decBS, cheb, N_, DEC_C_, 2.f);
        gemm_dense_k<64,64,16,4,4><<<dim3(2, ROWS_ / 64), 256>>>(cheb, DEC_CH_, duW, duB,
            nullptr, 0, DEC_CH_, DEC_, 2, haug, zr, 2 * DEC_);
        proj_k<<<(ROWS_ * 32 + 255) / 256, 256>>>(prW, prB, out, t);
    }
}